// round 1
// baseline (speedup 1.0000x reference)
#include <cuda_runtime.h>

#define BB 4
#define CI 256
#define CO 256
#define HH 64
#define WW 64
#define HW 4096
#define KD 2304          // CI * 9
#define MTOT 16384       // BB * HW

// ---------------- scratch (device globals; no allocation) ----------------
__device__ float g_poff[4 * BB * 18 * HW];          // partial offset-conv sums (4 c-quarters)
__device__ float g_off[BB * 18 * HW];               // final offsets
__device__ __align__(16) float g_wT[KD * CO];       // transposed weights [ck][o]
__device__ __align__(16) float g_raw[BB * CO * HW]; // pre-BN output
__device__ float g_scale[CO];
__device__ float g_shift[CO];

// ---------------- kernel 1: transpose w_conv[o][c][k] -> wT[ck][o] -------
__global__ void transpose_w(const float* __restrict__ w_conv) {
    int idx = blockIdx.x * 256 + threadIdx.x;   // over KD*CO
    if (idx < KD * CO) {
        int ck = idx >> 8;        // /256
        int o  = idx & 255;
        g_wT[idx] = w_conv[o * KD + ck];
    }
}

// ---------------- kernel 2: offset conv partials --------------------------
// grid (BB*HH, 4), block 64 threads (one pixel per thread, c-quarter per blockIdx.y)
__global__ void offset_partial(const float* __restrict__ x,
                               const float* __restrict__ w_off) {
    __shared__ __align__(16) float ws[8 * 162];   // 8 channels x (18 out x 9 taps), layout [ci][j*18+o]
    int bh = blockIdx.x;
    int cq = blockIdx.y;
    int b = bh >> 6, h = bh & 63;
    int w = threadIdx.x;

    float acc[18];
#pragma unroll
    for (int o = 0; o < 18; o++) acc[o] = 0.f;

    const float* xb = x + (size_t)b * CI * HW;

    for (int cc = 0; cc < 64; cc += 8) {
        int c0 = cq * 64 + cc;
        // stage weights for 8 channels: ws[ci*162 + j*18 + o]
        for (int e = threadIdx.x; e < 8 * 162; e += 64) {
            int ci = e / 162;
            int r  = e - ci * 162;
            int j  = r / 18;
            int o  = r - j * 18;
            ws[e] = w_off[o * KD + (c0 + ci) * 9 + j];
        }
        __syncthreads();

        for (int ci = 0; ci < 8; ci++) {
            int c = c0 + ci;
            const float* xc = xb + c * HW;
            float v[9];
#pragma unroll
            for (int ki = 0; ki < 3; ki++) {
                int yy = h + ki - 1;
                bool vy = (yy >= 0 && yy < HH);
#pragma unroll
                for (int kj = 0; kj < 3; kj++) {
                    int xx = w + kj - 1;
                    v[ki * 3 + kj] = (vy && xx >= 0 && xx < WW) ? xc[yy * WW + xx] : 0.f;
                }
            }
            const float2* wr2 = (const float2*)ws + ci * 81;
#pragma unroll
            for (int j = 0; j < 9; j++) {
                float vj = v[j];
#pragma unroll
                for (int p = 0; p < 9; p++) {
                    float2 ww = wr2[j * 9 + p];
                    acc[2 * p]     += vj * ww.x;
                    acc[2 * p + 1] += vj * ww.y;
                }
            }
        }
        __syncthreads();
    }
#pragma unroll
    for (int o = 0; o < 18; o++)
        g_poff[((cq * 4 + b) * 18 + o) * HW + h * WW + w] = acc[o];
}

// ---------------- kernel 3: reduce partials + bias ------------------------
__global__ void offset_reduce(const float* __restrict__ b_off) {
    int idx = blockIdx.x * 256 + threadIdx.x;
    if (idx >= BB * 18 * HW) return;
    int hw = idx & 4095;
    int bo = idx >> 12;          // b*18 + o
    int b = bo / 18;
    int o = bo - b * 18;
    float s = b_off[o];
#pragma unroll
    for (int cq = 0; cq < 4; cq++)
        s += g_poff[((cq * 4 + b) * 18 + o) * HW + hw];
    g_off[idx] = s;
}

// ---------------- kernel 4: deformable gather + GEMM (f32x2 FFMA2) --------
// Block tile 128(m) x 128(n), 256 threads, 8x8 per thread, KC=8.
__global__ __launch_bounds__(256, 2) void deform_gemm(const float* __restrict__ x) {
    __shared__ __align__(16) ushort4 gidx[128][9];                 // clipped corner indices
    __shared__ __align__(16) float4 gwts[128][9];                  // corner weights (validity folded)
    __shared__ int mbase[128];                                     // per-row batch base in x
    __shared__ __align__(16) unsigned long long As2[8][129];       // A duplicated {a,a}
    __shared__ __align__(16) float Bs[8][128];

    const int tid = threadIdx.x;
    const int m0 = blockIdx.x << 7;
    const int n0 = blockIdx.y << 7;

    // --- precompute bilinear corner table for 128 positions x 9 taps ---
    for (int e = tid; e < 128 * 9; e += 256) {
        int mm = e / 9;
        int k  = e - mm * 9;
        int m  = m0 + mm;
        int b  = m >> 12;
        int hw = m & 4095;
        int h  = hw >> 6;
        int w  = hw & 63;
        float offy = g_off[(b * 18 + 2 * k) * HW + hw];
        float offx = g_off[(b * 18 + 2 * k + 1) * HW + hw];
        int k3 = k / 3;
        float py = (float)(h + k3 - 1) + offy;
        float px = (float)(w + (k - k3 * 3) - 1) + offx;
        float fy0 = floorf(py), fx0 = floorf(px);
        float wy1 = py - fy0, wx1 = px - fx0;
        float wy0 = 1.f - wy1, wx0 = 1.f - wx1;
        int iy0 = (int)fy0, ix0 = (int)fx0;
        int iy1 = iy0 + 1, ix1 = ix0 + 1;
        float vy0 = (iy0 >= 0 && iy0 < HH) ? 1.f : 0.f;
        float vy1 = (iy1 >= 0 && iy1 < HH) ? 1.f : 0.f;
        float vx0 = (ix0 >= 0 && ix0 < WW) ? 1.f : 0.f;
        float vx1 = (ix1 >= 0 && ix1 < WW) ? 1.f : 0.f;
        int cy0 = min(max(iy0, 0), HH - 1), cy1 = min(max(iy1, 0), HH - 1);
        int cx0 = min(max(ix0, 0), WW - 1), cx1 = min(max(ix1, 0), WW - 1);
        ushort4 gi;
        gi.x = (unsigned short)(cy0 * WW + cx0);
        gi.y = (unsigned short)(cy0 * WW + cx1);
        gi.z = (unsigned short)(cy1 * WW + cx0);
        gi.w = (unsigned short)(cy1 * WW + cx1);
        gidx[mm][k] = gi;
        gwts[mm][k] = make_float4(wy0 * wx0 * vy0 * vx0,
                                  wy0 * wx1 * vy0 * vx1,
                                  wy1 * wx0 * vy1 * vx0,
                                  wy1 * wx1 * vy1 * vx1);
    }
    if (tid < 128) mbase[tid] = (((m0 + tid) >> 12) * CI) << 12;   // b * CI * HW
    __syncthreads();

    unsigned long long acc[8][4];
#pragma unroll
    for (int i = 0; i < 8; i++)
#pragma unroll
        for (int j = 0; j < 4; j++) acc[i][j] = 0ULL;

    const int ty = tid >> 4;
    const int tx = tid & 15;

    for (int kt = 0; kt < KD / 8; kt++) {
        // stage B: 8 x 128 floats
        {
            int kk = tid >> 5;
            int nn = (tid & 31) << 2;
            float4 bv = *(const float4*)(g_wT + (kt * 8 + kk) * CO + n0 + nn);
            *(float4*)(&Bs[kk][nn]) = bv;
        }
        // stage A: 128 x 8 elements, 4 per thread (bilinear gather)
#pragma unroll
        for (int rep = 0; rep < 4; rep++) {
            int e  = tid + (rep << 8);
            int mm = e >> 3;
            int kk = e & 7;
            int ck = kt * 8 + kk;
            int c  = ck / 9;
            int k  = ck - c * 9;
            ushort4 gi = gidx[mm][k];
            float4  gw = gwts[mm][k];
            const float* xc = x + mbase[mm] + (c << 12);
            float val = gw.x * __ldg(xc + gi.x)
                      + gw.y * __ldg(xc + gi.y)
                      + gw.z * __ldg(xc + gi.z)
                      + gw.w * __ldg(xc + gi.w);
            unsigned long long p;
            asm("mov.b64 %0, {%1, %1};" : "=l"(p) : "r"(__float_as_uint(val)));
            As2[kk][mm] = p;
        }
        __syncthreads();
        // compute: 8 kk steps of 8x8 f32x2 FMAs
#pragma unroll
        for (int kk = 0; kk < 8; kk++) {
            unsigned long long a2[8];
#pragma unroll
            for (int i = 0; i < 8; i++) a2[i] = As2[kk][ty * 8 + i];
            const unsigned long long* brow = (const unsigned long long*)(&Bs[kk][0]);
#pragma unroll
            for (int j = 0; j < 4; j++) {
                unsigned long long b2 = brow[tx * 4 + j];
#pragma unroll
                for (int i = 0; i < 8; i++)
                    asm("fma.rn.f32x2 %0, %1, %2, %0;"
                        : "+l"(acc[i][j]) : "l"(a2[i]), "l"(b2));
            }
        }
        __syncthreads();
    }

    // epilogue: write raw output (B, O, HW) layout, float4 stores
    const int b = m0 >> 12;
    const int hw0 = (m0 & 4095) + (ty << 3);
#pragma unroll
    for (int j = 0; j < 4; j++) {
        float lo[8], hi[8];
#pragma unroll
        for (int i = 0; i < 8; i++) {
            unsigned int ul, uh;
            asm("mov.b64 {%0, %1}, %2;" : "=r"(ul), "=r"(uh) : "l"(acc[i][j]));
            lo[i] = __uint_as_float(ul);
            hi[i] = __uint_as_float(uh);
        }
        int nlo = n0 + (tx << 3) + (j << 1);
        float* p0 = g_raw + (size_t)((b * CO + nlo) << 12) + hw0;
        float* p1 = p0 + HW;
        *(float4*)(p0)     = make_float4(lo[0], lo[1], lo[2], lo[3]);
        *(float4*)(p0 + 4) = make_float4(lo[4], lo[5], lo[6], lo[7]);
        *(float4*)(p1)     = make_float4(hi[0], hi[1], hi[2], hi[3]);
        *(float4*)(p1 + 4) = make_float4(hi[4], hi[5], hi[6], hi[7]);
    }
}

// ---------------- kernel 5: BN statistics per channel ---------------------
__global__ void bn_stats(const float* __restrict__ gamma,
                         const float* __restrict__ beta) {
    int o = blockIdx.x;
    int tid = threadIdx.x;
    float s = 0.f, s2 = 0.f;
#pragma unroll
    for (int b = 0; b < BB; b++) {
        const float* p = g_raw + (size_t)((b * CO + o) << 12);
        for (int i = tid; i < HW; i += 256) {
            float v = p[i];
            s += v;
            s2 += v * v;
        }
    }
    __shared__ float sh[256], sh2[256];
    sh[tid] = s; sh2[tid] = s2;
    __syncthreads();
    for (int st = 128; st > 0; st >>= 1) {
        if (tid < st) { sh[tid] += sh[tid + st]; sh2[tid] += sh2[tid + st]; }
        __syncthreads();
    }
    if (tid == 0) {
        float mean = sh[0] * (1.f / 16384.f);
        float var  = sh2[0] * (1.f / 16384.f) - mean * mean;
        float inv  = gamma[o] * rsqrtf(var + 1e-5f);
        g_scale[o] = inv;
        g_shift[o] = beta[o] - mean * inv;
    }
}

// ---------------- kernel 6: apply BN + ReLU -------------------------------
__global__ void bn_apply(float* __restrict__ out) {
    int t = blockIdx.x * 256 + threadIdx.x;   // float4 index, total 1048576
    int o = (t >> 10) & 255;
    float4 v = ((const float4*)g_raw)[t];
    float sc = g_scale[o], sf = g_shift[o];
    float4 r;
    r.x = fmaxf(v.x * sc + sf, 0.f);
    r.y = fmaxf(v.y * sc + sf, 0.f);
    r.z = fmaxf(v.z * sc + sf, 0.f);
    r.w = fmaxf(v.w * sc + sf, 0.f);
    ((float4*)out)[t] = r;
}

// ---------------- launch ---------------------------------------------------
extern "C" void kernel_launch(void* const* d_in, const int* in_sizes, int n_in,
                              void* d_out, int out_size) {
    const float* x      = (const float*)d_in[0];
    const float* w_off  = (const float*)d_in[1];
    const float* b_off  = (const float*)d_in[2];
    const float* w_conv = (const float*)d_in[3];
    const float* gamma  = (const float*)d_in[4];
    const float* beta   = (const float*)d_in[5];
    float* out = (float*)d_out;

    transpose_w<<<(KD * CO) / 256, 256>>>(w_conv);
    offset_partial<<<dim3(BB * HH, 4), 64>>>(x, w_off);
    offset_reduce<<<(BB * 18 * HW + 255) / 256, 256>>>(b_off);
    deform_gemm<<<dim3(MTOT / 128, CO / 128), 256>>>(x);
    bn_stats<<<CO, 256>>>(gamma, beta);
    bn_apply<<<(BB * CO * HW / 4) / 256, 256>>>(out);
}

// round 2
// speedup vs baseline: 1.4000x; 1.4000x over previous
#include <cuda_runtime.h>

#define BB 4
#define CI 256
#define CO 256
#define HH 64
#define WW 64
#define HW 4096
#define KD 2304          // CI * 9
#define MTOT 16384       // BB * HW
#define NKT 288          // KD / 8

// ---------------- scratch (device globals; no allocation) ----------------
__device__ float g_poff[4 * BB * 18 * HW];
__device__ float g_off[BB * 18 * HW];
__device__ __align__(16) float g_wT[KD * CO];       // transposed weights [ck][o]
__device__ __align__(16) float g_raw[BB * CO * HW]; // pre-BN output
__device__ float g_scale[CO];
__device__ float g_shift[CO];

// ---------------- kernel 1: transpose w_conv[o][c][k] -> wT[ck][o] -------
__global__ void transpose_w(const float* __restrict__ w_conv) {
    int idx = blockIdx.x * 256 + threadIdx.x;
    if (idx < KD * CO) {
        int ck = idx >> 8;
        int o  = idx & 255;
        g_wT[idx] = w_conv[o * KD + ck];
    }
}

// ---------------- kernel 2: offset conv partials (f32x2) ------------------
__global__ void offset_partial(const float* __restrict__ x,
                               const float* __restrict__ w_off) {
    __shared__ __align__(16) float ws[8 * 164];   // row stride 164 (8B-aligned rows)
    int bh = blockIdx.x;
    int cq = blockIdx.y;
    int b = bh >> 6, h = bh & 63;
    int w = threadIdx.x;

    unsigned long long acc2[9];
#pragma unroll
    for (int p = 0; p < 9; p++) acc2[p] = 0ULL;

    const float* xb = x + (size_t)b * CI * HW;

    for (int cc = 0; cc < 64; cc += 8) {
        int c0 = cq * 64 + cc;
        for (int e = threadIdx.x; e < 8 * 162; e += 64) {
            int ci = e / 162;
            int r  = e - ci * 162;
            int j  = r / 18;
            int o  = r - j * 18;
            ws[ci * 164 + j * 18 + o] = w_off[o * KD + (c0 + ci) * 9 + j];
        }
        __syncthreads();

        for (int ci = 0; ci < 8; ci++) {
            int c = c0 + ci;
            const float* xc = xb + c * HW;
            float v[9];
#pragma unroll
            for (int ki = 0; ki < 3; ki++) {
                int yy = h + ki - 1;
                bool vy = (yy >= 0 && yy < HH);
#pragma unroll
                for (int kj = 0; kj < 3; kj++) {
                    int xx = w + kj - 1;
                    v[ki * 3 + kj] = (vy && xx >= 0 && xx < WW) ? xc[yy * WW + xx] : 0.f;
                }
            }
#pragma unroll
            for (int j = 0; j < 9; j++) {
                unsigned long long a2;
                asm("mov.b64 %0, {%1, %1};" : "=l"(a2) : "r"(__float_as_uint(v[j])));
                const unsigned long long* ww2 =
                    (const unsigned long long*)(ws + ci * 164 + j * 18);
#pragma unroll
                for (int p = 0; p < 9; p++)
                    asm("fma.rn.f32x2 %0, %1, %2, %0;"
                        : "+l"(acc2[p]) : "l"(a2), "l"(ww2[p]));
            }
        }
        __syncthreads();
    }
#pragma unroll
    for (int p = 0; p < 9; p++) {
        unsigned int ul, uh;
        asm("mov.b64 {%0, %1}, %2;" : "=r"(ul), "=r"(uh) : "l"(acc2[p]));
        g_poff[((cq * 4 + b) * 18 + 2 * p)     * HW + h * WW + w] = __uint_as_float(ul);
        g_poff[((cq * 4 + b) * 18 + 2 * p + 1) * HW + h * WW + w] = __uint_as_float(uh);
    }
}

// ---------------- kernel 3: reduce partials + bias ------------------------
__global__ void offset_reduce(const float* __restrict__ b_off) {
    int idx = blockIdx.x * 256 + threadIdx.x;
    if (idx >= BB * 18 * HW) return;
    int hw = idx & 4095;
    int bo = idx >> 12;
    int b = bo / 18;
    int o = bo - b * 18;
    float s = b_off[o];
#pragma unroll
    for (int cq = 0; cq < 4; cq++)
        s += g_poff[((cq * 4 + b) * 18 + o) * HW + hw];
    g_off[idx] = s;
}

// ---------------- kernel 4: deformable gather + GEMM (f32x2, 2-stage) -----
// Block tile 64(m) x 256(n), 256 threads, 8x8 per thread, KC=8, double buffer.
__global__ __launch_bounds__(256, 2) void deform_gemm(const float* __restrict__ x) {
    __shared__ __align__(16) ushort4 gidx[9][64];                  // corner indices
    __shared__ __align__(16) float4  gwts[9][64];                  // corner weights
    __shared__ __align__(16) unsigned long long As[2][8][64];      // A duplicated {a,a}
    __shared__ __align__(16) unsigned long long Bs[2][8][128];     // B pairs (2n per u64)

    const int tid = threadIdx.x;
    const int m0 = blockIdx.x << 6;
    const int b  = m0 >> 12;
    const float* xb = x + (size_t)b * CI * HW;

    // --- precompute bilinear corner tables: 64 positions x 9 taps ---
    for (int e = tid; e < 9 * 64; e += 256) {
        int k  = e >> 6;
        int mm = e & 63;
        int m  = m0 + mm;
        int hw = m & 4095;
        int h  = hw >> 6;
        int w  = hw & 63;
        float offy = g_off[(b * 18 + 2 * k) * HW + hw];
        float offx = g_off[(b * 18 + 2 * k + 1) * HW + hw];
        int k3 = k / 3;
        float py = (float)(h + k3 - 1) + offy;
        float px = (float)(w + (k - k3 * 3) - 1) + offx;
        float fy0 = floorf(py), fx0 = floorf(px);
        float wy1 = py - fy0, wx1 = px - fx0;
        float wy0 = 1.f - wy1, wx0 = 1.f - wx1;
        int iy0 = (int)fy0, ix0 = (int)fx0;
        int iy1 = iy0 + 1, ix1 = ix0 + 1;
        float vy0 = (iy0 >= 0 && iy0 < HH) ? 1.f : 0.f;
        float vy1 = (iy1 >= 0 && iy1 < HH) ? 1.f : 0.f;
        float vx0 = (ix0 >= 0 && ix0 < WW) ? 1.f : 0.f;
        float vx1 = (ix1 >= 0 && ix1 < WW) ? 1.f : 0.f;
        int cy0 = min(max(iy0, 0), HH - 1), cy1 = min(max(iy1, 0), HH - 1);
        int cx0 = min(max(ix0, 0), WW - 1), cx1 = min(max(ix1, 0), WW - 1);
        ushort4 gi;
        gi.x = (unsigned short)(cy0 * WW + cx0);
        gi.y = (unsigned short)(cy0 * WW + cx1);
        gi.z = (unsigned short)(cy1 * WW + cx0);
        gi.w = (unsigned short)(cy1 * WW + cx1);
        gidx[k][mm] = gi;
        gwts[k][mm] = make_float4(wy0 * wx0 * vy0 * vx0,
                                  wy0 * wx1 * vy0 * vx1,
                                  wy1 * wx0 * vy1 * vx0,
                                  wy1 * wx1 * vy1 * vx1);
    }
    __syncthreads();

    const int tx = tid & 31;          // n-group
    const int ty = tid >> 5;          // m-group (0..7), one warp per ty
    const int bkk = tid >> 5;         // B-stage row
    const int bn  = (tid & 31) << 3;  // B-stage col

    // gather-stage element coords (2 per thread)
    const int gkk0 = tid >> 6;            // 0..3
    const int gmm  = tid & 63;

    unsigned long long acc[8][4];
#pragma unroll
    for (int i = 0; i < 8; i++)
#pragma unroll
        for (int j = 0; j < 4; j++) acc[i][j] = 0ULL;

    // ---- helper lambdas (inlined) ----
    auto load_B = [&](int kt, float4& b0, float4& b1) {
        const float* bg = g_wT + (size_t)(kt * 8 + bkk) * CO + bn;
        b0 = *(const float4*)bg;
        b1 = *(const float4*)(bg + 4);
    };
    auto load_A = [&](int kt, int rep, float4& corners, float4& wgt) {
        int kk = gkk0 + rep * 4;
        int ck = kt * 8 + kk;
        int c  = ck / 9;
        int k  = ck - c * 9;
        ushort4 gi = gidx[k][gmm];
        wgt = gwts[k][gmm];
        const float* xc = xb + (c << 12);
        corners.x = __ldg(xc + gi.x);
        corners.y = __ldg(xc + gi.y);
        corners.z = __ldg(xc + gi.z);
        corners.w = __ldg(xc + gi.w);
    };
    auto store_stage = [&](int buf, float4 b0, float4 b1,
                           float4 c0, float4 w0, float4 c1, float4 w1) {
        float* bsrow = (float*)&Bs[buf][bkk][0];
        *(float4*)(bsrow + bn)     = b0;
        *(float4*)(bsrow + bn + 4) = b1;
        float v0 = w0.x * c0.x + w0.y * c0.y + w0.z * c0.z + w0.w * c0.w;
        float v1 = w1.x * c1.x + w1.y * c1.y + w1.z * c1.z + w1.w * c1.w;
        unsigned long long p0, p1;
        asm("mov.b64 %0, {%1, %1};" : "=l"(p0) : "r"(__float_as_uint(v0)));
        asm("mov.b64 %0, {%1, %1};" : "=l"(p1) : "r"(__float_as_uint(v1)));
        As[buf][gkk0][gmm]     = p0;
        As[buf][gkk0 + 4][gmm] = p1;
    };

    // prologue: stage kt=0 into buf 0
    {
        float4 b0, b1, c0, w0, c1, w1;
        load_B(0, b0, b1);
        load_A(0, 0, c0, w0);
        load_A(0, 1, c1, w1);
        store_stage(0, b0, b1, c0, w0, c1, w1);
    }
    __syncthreads();

    for (int kt = 0; kt < NKT; kt++) {
        int buf = kt & 1;
        bool pf = (kt + 1 < NKT);
        float4 b0, b1, c0, w0, c1, w1;
        if (pf) {
            load_B(kt + 1, b0, b1);
            load_A(kt + 1, 0, c0, w0);
            load_A(kt + 1, 1, c1, w1);
        }
        // compute on buf
#pragma unroll
        for (int kk = 0; kk < 8; kk++) {
            unsigned long long a2[8];
            const unsigned long long* ap = &As[buf][kk][ty * 8];
#pragma unroll
            for (int i = 0; i < 8; i++) a2[i] = ap[i];
            const unsigned long long* bp = &Bs[buf][kk][0];
#pragma unroll
            for (int j = 0; j < 4; j++) {
                unsigned long long b2 = bp[tx + 32 * j];
#pragma unroll
                for (int i = 0; i < 8; i++)
                    asm("fma.rn.f32x2 %0, %1, %2, %0;"
                        : "+l"(acc[i][j]) : "l"(a2[i]), "l"(b2));
            }
        }
        if (pf) store_stage(buf ^ 1, b0, b1, c0, w0, c1, w1);
        __syncthreads();
    }

    // epilogue: thread covers m = m0 + ty*8 + i, n pair = (2tx + 64j, +1)
    const int hw0 = (m0 & 4095) + (ty << 3);
#pragma unroll
    for (int j = 0; j < 4; j++) {
        float lo[8], hi[8];
#pragma unroll
        for (int i = 0; i < 8; i++) {
            unsigned int ul, uh;
            asm("mov.b64 {%0, %1}, %2;" : "=r"(ul), "=r"(uh) : "l"(acc[i][j]));
            lo[i] = __uint_as_float(ul);
            hi[i] = __uint_as_float(uh);
        }
        int nlo = 2 * tx + 64 * j;
        float* p0 = g_raw + (size_t)((b * CO + nlo) << 12) + hw0;
        float* p1 = p0 + HW;
        *(float4*)(p0)     = make_float4(lo[0], lo[1], lo[2], lo[3]);
        *(float4*)(p0 + 4) = make_float4(lo[4], lo[5], lo[6], lo[7]);
        *(float4*)(p1)     = make_float4(hi[0], hi[1], hi[2], hi[3]);
        *(float4*)(p1 + 4) = make_float4(hi[4], hi[5], hi[6], hi[7]);
    }
}

// ---------------- kernel 5: BN statistics per channel ---------------------
__global__ void bn_stats(const float* __restrict__ gamma,
                         const float* __restrict__ beta) {
    int o = blockIdx.x;
    int tid = threadIdx.x;
    float s = 0.f, s2 = 0.f;
#pragma unroll
    for (int b = 0; b < BB; b++) {
        const float* p = g_raw + (size_t)((b * CO + o) << 12);
        for (int i = tid; i < HW; i += 256) {
            float v = p[i];
            s += v;
            s2 += v * v;
        }
    }
    __shared__ float sh[256], sh2[256];
    sh[tid] = s; sh2[tid] = s2;
    __syncthreads();
    for (int st = 128; st > 0; st >>= 1) {
        if (tid < st) { sh[tid] += sh[tid + st]; sh2[tid] += sh2[tid + st]; }
        __syncthreads();
    }
    if (tid == 0) {
        float mean = sh[0] * (1.f / 16384.f);
        float var  = sh2[0] * (1.f / 16384.f) - mean * mean;
        float inv  = gamma[o] * rsqrtf(var + 1e-5f);
        g_scale[o] = inv;
        g_shift[o] = beta[o] - mean * inv;
    }
}

// ---------------- kernel 6: apply BN + ReLU -------------------------------
__global__ void bn_apply(float* __restrict__ out) {
    int t = blockIdx.x * 256 + threadIdx.x;
    int o = (t >> 10) & 255;
    float4 v = ((const float4*)g_raw)[t];
    float sc = g_scale[o], sf = g_shift[o];
    float4 r;
    r.x = fmaxf(v.x * sc + sf, 0.f);
    r.y = fmaxf(v.y * sc + sf, 0.f);
    r.z = fmaxf(v.z * sc + sf, 0.f);
    r.w = fmaxf(v.w * sc + sf, 0.f);
    ((float4*)out)[t] = r;
}

// ---------------- launch ---------------------------------------------------
extern "C" void kernel_launch(void* const* d_in, const int* in_sizes, int n_in,
                              void* d_out, int out_size) {
    const float* x      = (const float*)d_in[0];
    const float* w_off  = (const float*)d_in[1];
    const float* b_off  = (const float*)d_in[2];
    const float* w_conv = (const float*)d_in[3];
    const float* gamma  = (const float*)d_in[4];
    const float* beta   = (const float*)d_in[5];
    float* out = (float*)d_out;

    transpose_w<<<(KD * CO) / 256, 256>>>(w_conv);
    offset_partial<<<dim3(BB * HH, 4), 64>>>(x, w_off);
    offset_reduce<<<(BB * 18 * HW + 255) / 256, 256>>>(b_off);
    deform_gemm<<<MTOT / 64, 256>>>(x);
    bn_stats<<<CO, 256>>>(gamma, beta);
    bn_apply<<<(BB * CO * HW / 4) / 256, 256>>>(out);
}

// round 4
// speedup vs baseline: 3.3008x; 2.3577x over previous
#include <cuda_runtime.h>
#include <cstdint>

#define BB 4
#define CI 256
#define CO 256
#define HH 64
#define WW 64
#define HW 4096
#define KD 2304          // CI * 9
#define MTOT 16384
#define KC 32
#define NCHUNK 72        // KD / KC

// ---------------- scratch ----------------
__device__ float g_poff[4 * BB * 18 * HW];
__device__ float g_off[BB * 18 * HW];
__device__ __align__(16) uint32_t g_wB[NCHUNK * 8192];   // frag-ordered tf32 B tiles
__device__ __align__(16) float g_raw[BB * CO * HW];
__device__ float g_scale[CO];
__device__ float g_shift[CO];

// ---------------- helpers ----------------
__device__ __forceinline__ uint32_t smem_u32(const void* p) {
    uint32_t a;
    asm("{ .reg .u64 t; cvta.to.shared.u64 t, %1; cvt.u32.u64 %0, t; }" : "=r"(a) : "l"(p));
    return a;
}
__device__ __forceinline__ uint32_t f2tf32(float f) {
    uint32_t r;
    asm("cvt.rna.tf32.f32 %0, %1;" : "=r"(r) : "f"(f));
    return r;
}
__device__ __forceinline__ void mma_tf32(float* d, const uint32_t* a,
                                         uint32_t b0, uint32_t b1) {
    asm volatile(
        "mma.sync.aligned.m16n8k8.row.col.f32.tf32.tf32.f32 "
        "{%0,%1,%2,%3}, {%4,%5,%6,%7}, {%8,%9}, {%0,%1,%2,%3};"
        : "+f"(d[0]), "+f"(d[1]), "+f"(d[2]), "+f"(d[3])
        : "r"(a[0]), "r"(a[1]), "r"(a[2]), "r"(a[3]), "r"(b0), "r"(b1));
}
__device__ __forceinline__ void cp_async16(uint32_t saddr, const void* gaddr) {
    asm volatile("cp.async.cg.shared.global [%0], [%1], 16;" :: "r"(saddr), "l"(gaddr));
}

// ---------------- kernel: pack B into fragment order (tf32) ---------------
// layout per kt: [ks(4)][ntile(32)][lane(32)][2]
__global__ void prep_wB(const float* __restrict__ w_conv) {
    int idx = blockIdx.x * 256 + threadIdx.x;
    if (idx >= NCHUNK * 8192) return;
    int kt = idx >> 13;
    int r  = idx & 8191;
    int ks   = r >> 11;
    int nt   = (r >> 6) & 31;
    int lane = (r >> 1) & 31;
    int h    = r & 1;
    int g = lane >> 2, tg = lane & 3;
    int n  = nt * 8 + g;
    int kk = ks * 8 + tg + 4 * h;
    int ck = kt * KC + kk;
    g_wB[idx] = f2tf32(w_conv[n * KD + ck]);
}

// ---------------- offset conv partials -------------------------------------
__global__ void offset_partial(const float* __restrict__ x,
                               const float* __restrict__ w_off) {
    __shared__ __align__(16) float ws[8 * 164];
    int b  = blockIdx.x >> 4;
    int hq = blockIdx.x & 15;
    int cq = blockIdx.y;
    int tid = threadIdx.x;
    int h = hq * 4 + (tid >> 6);
    int w = tid & 63;

    unsigned long long acc2[9];
#pragma unroll
    for (int p = 0; p < 9; p++) acc2[p] = 0ULL;

    const float* xb = x + (size_t)b * CI * HW;

    for (int cc = 0; cc < 64; cc += 8) {
        int c0 = cq * 64 + cc;
        for (int e = tid; e < 8 * 162; e += 256) {
            int ci = e / 162;
            int r  = e - ci * 162;
            int j  = r / 18;
            int o  = r - j * 18;
            ws[ci * 164 + j * 18 + o] = w_off[o * KD + (c0 + ci) * 9 + j];
        }
        __syncthreads();

        for (int ci = 0; ci < 8; ci++) {
            const float* xc = xb + (c0 + ci) * HW;
            float v[9];
#pragma unroll
            for (int ki = 0; ki < 3; ki++) {
                int yy = h + ki - 1;
                bool vy = (yy >= 0 && yy < HH);
#pragma unroll
                for (int kj = 0; kj < 3; kj++) {
                    int xx = w + kj - 1;
                    v[ki * 3 + kj] = (vy && xx >= 0 && xx < WW) ? xc[yy * WW + xx] : 0.f;
                }
            }
#pragma unroll
            for (int j = 0; j < 9; j++) {
                unsigned long long a2;
                asm("mov.b64 %0, {%1, %1};" : "=l"(a2) : "r"(__float_as_uint(v[j])));
                const unsigned long long* ww2 =
                    (const unsigned long long*)(ws + ci * 164 + j * 18);
#pragma unroll
                for (int p = 0; p < 9; p++)
                    asm("fma.rn.f32x2 %0, %1, %2, %0;"
                        : "+l"(acc2[p]) : "l"(a2), "l"(ww2[p]));
            }
        }
        __syncthreads();
    }
#pragma unroll
    for (int p = 0; p < 9; p++) {
        unsigned int ul, uh;
        asm("mov.b64 {%0, %1}, %2;" : "=r"(ul), "=r"(uh) : "l"(acc2[p]));
        g_poff[((cq * 4 + b) * 18 + 2 * p)     * HW + h * WW + w] = __uint_as_float(ul);
        g_poff[((cq * 4 + b) * 18 + 2 * p + 1) * HW + h * WW + w] = __uint_as_float(uh);
    }
}

__global__ void offset_reduce(const float* __restrict__ b_off) {
    int idx = blockIdx.x * 256 + threadIdx.x;
    if (idx >= BB * 18 * HW) return;
    int hw = idx & 4095;
    int bo = idx >> 12;
    int b = bo / 18;
    int o = bo - b * 18;
    float s = b_off[o];
#pragma unroll
    for (int cq = 0; cq < 4; cq++)
        s += g_poff[((cq * 4 + b) * 18 + o) * HW + hw];
    g_off[idx] = s;
}

// ---------------- deformable gather + HMMA tf32 GEMM -----------------------
// SMEM layout (dynamic, bytes)
#define OFF_GIDX 0                        // ushort4[9*128] = 9216
#define OFF_GWTS 9216                     // float4[9*128]  = 18432 -> 27648
#define OFF_A    27648                    // 2 * 16384 -> 60416
#define OFF_B    60416                    // 2 * 32768 -> 125952
#define SMEM_TOTAL 125952

// A swizzle: word index = m*32 + ((k + 4*(m&7) + ((m>>3)&3)) & 31)
__device__ __forceinline__ int a_word(int m, int k) {
    return m * 32 + ((k + 4 * (m & 7) + ((m >> 3) & 3)) & 31);
}

__global__ void __launch_bounds__(512, 1)
deform_gemm_tc(const float* __restrict__ x) {
    extern __shared__ char smem[];
    const uint32_t sb = smem_u32(smem);
    ushort4*  gidx = (ushort4*)(smem + OFF_GIDX);
    float4*   gwts = (float4*)(smem + OFF_GWTS);
    uint32_t* As   = (uint32_t*)(smem + OFF_A);
    uint32_t* Bs   = (uint32_t*)(smem + OFF_B);

    const int tid  = threadIdx.x;
    const int wid  = tid >> 5;
    const int lane = tid & 31;
    const int g  = lane >> 2;
    const int tg = lane & 3;
    const int m0 = blockIdx.x << 7;
    const int b  = m0 >> 12;
    const float* xb = x + (size_t)b * CI * HW;

    // bilinear corner tables: 9 taps x 128 positions
    for (int e = tid; e < 9 * 128; e += 512) {
        int k  = e >> 7;
        int mm = e & 127;
        int hw = (m0 + mm) & 4095;
        int h  = hw >> 6;
        int w  = hw & 63;
        float offy = g_off[(b * 18 + 2 * k) * HW + hw];
        float offx = g_off[(b * 18 + 2 * k + 1) * HW + hw];
        int k3 = k / 3;
        float py = (float)(h + k3 - 1) + offy;
        float px = (float)(w + (k - k3 * 3) - 1) + offx;
        float fy0 = floorf(py), fx0 = floorf(px);
        float wy1 = py - fy0, wx1 = px - fx0;
        float wy0 = 1.f - wy1, wx0 = 1.f - wx1;
        int iy0 = (int)fy0, ix0 = (int)fx0;
        int iy1 = iy0 + 1, ix1 = ix0 + 1;
        float vy0 = (iy0 >= 0 && iy0 < HH) ? 1.f : 0.f;
        float vy1 = (iy1 >= 0 && iy1 < HH) ? 1.f : 0.f;
        float vx0 = (ix0 >= 0 && ix0 < WW) ? 1.f : 0.f;
        float vx1 = (ix1 >= 0 && ix1 < WW) ? 1.f : 0.f;
        int cy0 = min(max(iy0, 0), HH - 1), cy1 = min(max(iy1, 0), HH - 1);
        int cx0 = min(max(ix0, 0), WW - 1), cx1 = min(max(ix1, 0), WW - 1);
        ushort4 gi;
        gi.x = (unsigned short)(cy0 * WW + cx0);
        gi.y = (unsigned short)(cy0 * WW + cx1);
        gi.z = (unsigned short)(cy1 * WW + cx0);
        gi.w = (unsigned short)(cy1 * WW + cx1);
        gidx[e] = gi;
        gwts[e] = make_float4(wy0 * wx0 * vy0 * vx0,
                              wy0 * wx1 * vy0 * vx1,
                              wy1 * wx0 * vy1 * vx0,
                              wy1 * wx1 * vy1 * vx1);
    }
    __syncthreads();

    // gather task: warp covers mm-block of 32 rows x kk-block of 8
    const int mmb = (wid & 3) * 32;
    const int kkb = (wid >> 2) * 8;
    const int mm  = mmb + lane;
    const int msw = 4 * (mm & 7) + ((mm >> 3) & 3);   // swizzle add for this row

    // compute task: warp = (wm, wn) in 4x4 grid; m 32 rows, n 64 cols
    const int wm = wid & 3;
    const int wn = wid >> 2;

    float acc[2][8][4];
#pragma unroll
    for (int mt = 0; mt < 2; mt++)
#pragma unroll
        for (int nt = 0; nt < 8; nt++)
#pragma unroll
            for (int r = 0; r < 4; r++) acc[mt][nt][r] = 0.f;

    float cor[16];

    auto copy_B = [&](int kt, int buf) {
        uint32_t bdst = sb + OFF_B + buf * 32768;
        const float4* bsrc = (const float4*)(g_wB + (size_t)kt * 8192);
#pragma unroll
        for (int r = 0; r < 4; r++)
            cp_async16(bdst + (r * 512 + tid) * 16, bsrc + r * 512 + tid);
        asm volatile("cp.async.commit_group;" ::: "memory");
    };
    auto gather_load = [&](int kt, int grp) {
#pragma unroll
        for (int s = 0; s < 4; s++) {
            int ck = kt * KC + kkb + grp * 4 + s;
            int c  = ck / 9;
            int kt9 = ck - c * 9;
            ushort4 gi = gidx[kt9 * 128 + mm];
            const float* xc = xb + (c << 12);
            cor[4 * s + 0] = __ldg(xc + gi.x);
            cor[4 * s + 1] = __ldg(xc + gi.y);
            cor[4 * s + 2] = __ldg(xc + gi.z);
            cor[4 * s + 3] = __ldg(xc + gi.w);
        }
    };
    auto gather_store = [&](int kt, int grp, int buf) {
        uint32_t* ab = As + buf * 4096;
#pragma unroll
        for (int s = 0; s < 4; s++) {
            int kk = kkb + grp * 4 + s;
            int ck = kt * KC + kk;
            int c  = ck / 9;
            int kt9 = ck - c * 9;
            float4 wv = gwts[kt9 * 128 + mm];
            float v = wv.x * cor[4 * s] + wv.y * cor[4 * s + 1]
                    + wv.z * cor[4 * s + 2] + wv.w * cor[4 * s + 3];
            ab[mm * 32 + ((kk + msw) & 31)] = f2tf32(v);
        }
    };
    auto compute2 = [&](int buf, int half) {
        const uint32_t* ab = As + buf * 4096;
        const uint32_t* bb = Bs + buf * 8192;
#pragma unroll
        for (int kh = 0; kh < 2; kh++) {
            int k8 = half * 2 + kh;
            uint32_t a[2][4];
#pragma unroll
            for (int mt = 0; mt < 2; mt++) {
                int mr = wm * 32 + mt * 16;
                a[mt][0] = ab[a_word(mr + g,     k8 * 8 + tg)];
                a[mt][1] = ab[a_word(mr + g + 8, k8 * 8 + tg)];
                a[mt][2] = ab[a_word(mr + g,     k8 * 8 + tg + 4)];
                a[mt][3] = ab[a_word(mr + g + 8, k8 * 8 + tg + 4)];
            }
#pragma unroll
            for (int nt = 0; nt < 8; nt++) {
                uint32_t b0, b1;
                uint32_t addr = sb + OFF_B + buf * 32768
                              + (((k8 * 32) + (wn * 8 + nt)) * 32 + lane) * 8;
                asm volatile("ld.shared.v2.u32 {%0,%1}, [%2];"
                             : "=r"(b0), "=r"(b1) : "r"(addr));
                (void)bb;
                mma_tf32(acc[0][nt], a[0], b0, b1);
                mma_tf32(acc[1][nt], a[1], b0, b1);
            }
        }
    };

    // prologue: stage kt=0 into buf 0
    copy_B(0, 0);
    gather_load(0, 0); gather_store(0, 0, 0);
    gather_load(0, 1); gather_store(0, 1, 0);
    asm volatile("cp.async.wait_group 0;" ::: "memory");
    __syncthreads();

    for (int kt = 0; kt < NCHUNK; kt++) {
        int buf = kt & 1;
        bool pf = (kt + 1 < NCHUNK);
        if (pf) {
            copy_B(kt + 1, buf ^ 1);
            gather_load(kt + 1, 0);
        }
        compute2(buf, 0);
        if (pf) {
            gather_store(kt + 1, 0, buf ^ 1);
            gather_load(kt + 1, 1);
        }
        compute2(buf, 1);
        if (pf) gather_store(kt + 1, 1, buf ^ 1);
        asm volatile("cp.async.wait_group 0;" ::: "memory");
        __syncthreads();
    }

    // epilogue: acc -> g_raw[b][n][hw]
    const int hwb = (m0 & 4095);
#pragma unroll
    for (int mt = 0; mt < 2; mt++) {
        int hw0 = hwb + wm * 32 + mt * 16 + g;
#pragma unroll
        for (int nt = 0; nt < 8; nt++) {
            int n = wn * 64 + nt * 8 + 2 * tg;
            float* p0 = g_raw + ((size_t)(b * CO + n) << 12);
            float* p1 = p0 + HW;
            p0[hw0]     = acc[mt][nt][0];
            p1[hw0]     = acc[mt][nt][1];
            p0[hw0 + 8] = acc[mt][nt][2];
            p1[hw0 + 8] = acc[mt][nt][3];
        }
    }
}

// ---------------- BN ----------------
__global__ void bn_stats(const float* __restrict__ gamma,
                         const float* __restrict__ beta) {
    int o = blockIdx.x;
    int tid = threadIdx.x;
    float s = 0.f, s2 = 0.f;
#pragma unroll
    for (int b = 0; b < BB; b++) {
        const float* p = g_raw + (size_t)((b * CO + o) << 12);
        for (int i = tid; i < HW; i += 256) {
            float v = p[i];
            s += v;
            s2 += v * v;
        }
    }
    __shared__ float sh[256], sh2[256];
    sh[tid] = s; sh2[tid] = s2;
    __syncthreads();
    for (int st = 128; st > 0; st >>= 1) {
        if (tid < st) { sh[tid] += sh[tid + st]; sh2[tid] += sh2[tid + st]; }
        __syncthreads();
    }
    if (tid == 0) {
        float mean = sh[0] * (1.f / 16384.f);
        float var  = sh2[0] * (1.f / 16384.f) - mean * mean;
        float inv  = gamma[o] * rsqrtf(var + 1e-5f);
        g_scale[o] = inv;
        g_shift[o] = beta[o] - mean * inv;
    }
}

__global__ void bn_apply(float* __restrict__ out) {
    int t = blockIdx.x * 256 + threadIdx.x;
    int o = (t >> 10) & 255;
    float4 v = ((const float4*)g_raw)[t];
    float sc = g_scale[o], sf = g_shift[o];
    float4 r;
    r.x = fmaxf(v.x * sc + sf, 0.f);
    r.y = fmaxf(v.y * sc + sf, 0.f);
    r.z = fmaxf(v.z * sc + sf, 0.f);
    r.w = fmaxf(v.w * sc + sf, 0.f);
    ((float4*)out)[t] = r;
}

// ---------------- launch ----------------
extern "C" void kernel_launch(void* const* d_in, const int* in_sizes, int n_in,
                              void* d_out, int out_size) {
    const float* x      = (const float*)d_in[0];
    const float* w_off  = (const float*)d_in[1];
    const float* b_off  = (const float*)d_in[2];
    const float* w_conv = (const float*)d_in[3];
    const float* gamma  = (const float*)d_in[4];
    const float* beta   = (const float*)d_in[5];
    float* out = (float*)d_out;

    cudaFuncSetAttribute(deform_gemm_tc,
                         cudaFuncAttributeMaxDynamicSharedMemorySize, SMEM_TOTAL);

    prep_wB<<<(NCHUNK * 8192) / 256, 256>>>(w_conv);
    offset_partial<<<dim3(BB * 16, 4), 256>>>(x, w_off);
    offset_reduce<<<(BB * 18 * HW + 255) / 256, 256>>>(b_off);
    deform_gemm_tc<<<MTOT / 128, 512, SMEM_TOTAL>>>(x);
    bn_stats<<<CO, 256>>>(gamma, beta);
    bn_apply<<<(BB * CO * HW / 4) / 256, 256>>>(out);
}

// round 5
// speedup vs baseline: 4.1772x; 1.2655x over previous
#include <cuda_runtime.h>
#include <cuda_fp16.h>
#include <cstdint>

#define BB 4
#define CI 256
#define CO 256
#define HH 64
#define WW 64
#define HW 4096
#define KD 2304          // CI * 9
#define MTOT 16384
#define KC 32
#define NCHUNK 72        // KD / KC

// ---------------- scratch ----------------
__device__ float g_poff[4 * BB * 18 * HW];
__device__ float g_off[BB * 18 * HW];
__device__ __align__(16) uint32_t g_wB[NCHUNK * 4096];   // frag-ordered fp16 B tiles
__device__ __align__(16) float g_raw[BB * CO * HW];
__device__ float g_scale[CO];
__device__ float g_shift[CO];

// ---------------- helpers ----------------
__device__ __forceinline__ uint32_t smem_u32(const void* p) {
    uint32_t a;
    asm("{ .reg .u64 t; cvta.to.shared.u64 t, %1; cvt.u32.u64 %0, t; }" : "=r"(a) : "l"(p));
    return a;
}
__device__ __forceinline__ uint32_t pack_h2(float lo, float hi) {
    __half2 h = __floats2half2_rn(lo, hi);
    return *(uint32_t*)&h;
}
__device__ __forceinline__ void mma_f16(float* d, const uint32_t* a,
                                        uint32_t b0, uint32_t b1) {
    asm volatile(
        "mma.sync.aligned.m16n8k16.row.col.f32.f16.f16.f32 "
        "{%0,%1,%2,%3}, {%4,%5,%6,%7}, {%8,%9}, {%0,%1,%2,%3};"
        : "+f"(d[0]), "+f"(d[1]), "+f"(d[2]), "+f"(d[3])
        : "r"(a[0]), "r"(a[1]), "r"(a[2]), "r"(a[3]), "r"(b0), "r"(b1));
}
__device__ __forceinline__ void cp_async16(uint32_t saddr, const void* gaddr) {
    asm volatile("cp.async.cg.shared.global [%0], [%1], 16;" :: "r"(saddr), "l"(gaddr));
}
// A swizzle shift for row m (mod-16 additive, conflict-free stores and loads)
__device__ __forceinline__ int a_sw(int m) {
    return 4 * ((m >> 1) & 3) + ((m >> 3) & 3);
}

// ---------------- kernel: pack B into fragment order (fp16) ---------------
// layout per kt: [k16(2)][np(16)][lane(32)][w(4)]; word w: nt=np*2+(w>>1), h=w&1
__global__ void prep_wB(const float* __restrict__ w_conv) {
    int idx = blockIdx.x * 256 + threadIdx.x;
    if (idx >= NCHUNK * 4096) return;
    int kt = idx >> 12;
    int r  = idx & 4095;
    int k16  = r >> 11;
    int np   = (r >> 7) & 15;
    int lane = (r >> 2) & 31;
    int w    = r & 3;
    int g = lane >> 2, tg = lane & 3;
    int nt = np * 2 + (w >> 1);
    int h  = w & 1;
    int n  = nt * 8 + g;
    int ck = kt * KC + k16 * 16 + h * 8 + 2 * tg;
    g_wB[idx] = pack_h2(w_conv[n * KD + ck], w_conv[n * KD + ck + 1]);
}

// ---------------- offset conv partials -------------------------------------
__global__ void offset_partial(const float* __restrict__ x,
                               const float* __restrict__ w_off) {
    __shared__ __align__(16) float ws[8 * 164];
    int b  = blockIdx.x >> 4;
    int hq = blockIdx.x & 15;
    int cq = blockIdx.y;
    int tid = threadIdx.x;
    int h = hq * 4 + (tid >> 6);
    int w = tid & 63;

    unsigned long long acc2[9];
#pragma unroll
    for (int p = 0; p < 9; p++) acc2[p] = 0ULL;

    const float* xb = x + (size_t)b * CI * HW;

    for (int cc = 0; cc < 64; cc += 8) {
        int c0 = cq * 64 + cc;
        for (int e = tid; e < 8 * 162; e += 256) {
            int ci = e / 162;
            int r  = e - ci * 162;
            int j  = r / 18;
            int o  = r - j * 18;
            ws[ci * 164 + j * 18 + o] = w_off[o * KD + (c0 + ci) * 9 + j];
        }
        __syncthreads();

        for (int ci = 0; ci < 8; ci++) {
            const float* xc = xb + (c0 + ci) * HW;
            float v[9];
#pragma unroll
            for (int ki = 0; ki < 3; ki++) {
                int yy = h + ki - 1;
                bool vy = (yy >= 0 && yy < HH);
#pragma unroll
                for (int kj = 0; kj < 3; kj++) {
                    int xx = w + kj - 1;
                    v[ki * 3 + kj] = (vy && xx >= 0 && xx < WW) ? xc[yy * WW + xx] : 0.f;
                }
            }
#pragma unroll
            for (int j = 0; j < 9; j++) {
                unsigned long long a2;
                asm("mov.b64 %0, {%1, %1};" : "=l"(a2) : "r"(__float_as_uint(v[j])));
                const unsigned long long* ww2 =
                    (const unsigned long long*)(ws + ci * 164 + j * 18);
#pragma unroll
                for (int p = 0; p < 9; p++)
                    asm("fma.rn.f32x2 %0, %1, %2, %0;"
                        : "+l"(acc2[p]) : "l"(a2), "l"(ww2[p]));
            }
        }
        __syncthreads();
    }
#pragma unroll
    for (int p = 0; p < 9; p++) {
        unsigned int ul, uh;
        asm("mov.b64 {%0, %1}, %2;" : "=r"(ul), "=r"(uh) : "l"(acc2[p]));
        g_poff[((cq * 4 + b) * 18 + 2 * p)     * HW + h * WW + w] = __uint_as_float(ul);
        g_poff[((cq * 4 + b) * 18 + 2 * p + 1) * HW + h * WW + w] = __uint_as_float(uh);
    }
}

__global__ void offset_reduce(const float* __restrict__ b_off) {
    int idx = blockIdx.x * 256 + threadIdx.x;
    if (idx >= BB * 18 * HW) return;
    int hw = idx & 4095;
    int bo = idx >> 12;
    int b = bo / 18;
    int o = bo - b * 18;
    float s = b_off[o];
#pragma unroll
    for (int cq = 0; cq < 4; cq++)
        s += g_poff[((cq * 4 + b) * 18 + o) * HW + hw];
    g_off[idx] = s;
}

// ---------------- deformable gather + HMMA fp16 GEMM -----------------------
// SMEM layout (dynamic, bytes)
#define OFF_GIDX 0                        // ushort4[9*128] = 9216
#define OFF_GWTS 9216                     // float4[9*128]  = 18432 -> 27648
#define OFF_A    27648                    // 2 * 8192  -> 44032
#define OFF_B    44032                    // 2 * 16384 -> 76800
#define SMEM_TOTAL 76800

__global__ void __launch_bounds__(512, 1)
deform_gemm_tc(const float* __restrict__ x) {
    extern __shared__ char smem[];
    const uint32_t sb = smem_u32(smem);
    ushort4*  gidx = (ushort4*)(smem + OFF_GIDX);
    float4*   gwts = (float4*)(smem + OFF_GWTS);
    uint32_t* As   = (uint32_t*)(smem + OFF_A);

    const int tid  = threadIdx.x;
    const int wid  = tid >> 5;
    const int lane = tid & 31;
    const int g  = lane >> 2;
    const int tg = lane & 3;
    const int m0 = blockIdx.x << 7;
    const int b  = m0 >> 12;
    const float* xb = x + (size_t)b * CI * HW;

    // bilinear corner tables: 9 taps x 128 positions
    for (int e = tid; e < 9 * 128; e += 512) {
        int k  = e >> 7;
        int mm = e & 127;
        int hw = (m0 + mm) & 4095;
        int h  = hw >> 6;
        int w  = hw & 63;
        float offy = g_off[(b * 18 + 2 * k) * HW + hw];
        float offx = g_off[(b * 18 + 2 * k + 1) * HW + hw];
        int k3 = k / 3;
        float py = (float)(h + k3 - 1) + offy;
        float px = (float)(w + (k - k3 * 3) - 1) + offx;
        float fy0 = floorf(py), fx0 = floorf(px);
        float wy1 = py - fy0, wx1 = px - fx0;
        float wy0 = 1.f - wy1, wx0 = 1.f - wx1;
        int iy0 = (int)fy0, ix0 = (int)fx0;
        int iy1 = iy0 + 1, ix1 = ix0 + 1;
        float vy0 = (iy0 >= 0 && iy0 < HH) ? 1.f : 0.f;
        float vy1 = (iy1 >= 0 && iy1 < HH) ? 1.f : 0.f;
        float vx0 = (ix0 >= 0 && ix0 < WW) ? 1.f : 0.f;
        float vx1 = (ix1 >= 0 && ix1 < WW) ? 1.f : 0.f;
        int cy0 = min(max(iy0, 0), HH - 1), cy1 = min(max(iy1, 0), HH - 1);
        int cx0 = min(max(ix0, 0), WW - 1), cx1 = min(max(ix1, 0), WW - 1);
        ushort4 gi;
        gi.x = (unsigned short)(cy0 * WW + cx0);
        gi.y = (unsigned short)(cy0 * WW + cx1);
        gi.z = (unsigned short)(cy1 * WW + cx0);
        gi.w = (unsigned short)(cy1 * WW + cx1);
        gidx[e] = gi;
        gwts[e] = make_float4(wy0 * wx0 * vy0 * vx0,
                              wy0 * wx1 * vy0 * vx1,
                              wy1 * wx0 * vy1 * vx0,
                              wy1 * wx1 * vy1 * vx1);
    }
    __syncthreads();

    // gather task: warp covers mm-block of 32 rows x kk-block of 8
    const int mmb = (wid & 3) * 32;
    const int kkb = (wid >> 2) * 8;
    const int mm  = mmb + lane;
    const int msw = a_sw(mm);

    // compute task: warp = (wm, wn) in 4x4 grid; m 32 rows, n 64 cols
    const int wm = wid & 3;
    const int wn = wid >> 2;

    float acc[2][8][4];
#pragma unroll
    for (int mt = 0; mt < 2; mt++)
#pragma unroll
        for (int nt = 0; nt < 8; nt++)
#pragma unroll
            for (int r = 0; r < 4; r++) acc[mt][nt][r] = 0.f;

    float cor[16];

    auto copy_B = [&](int kt, int buf) {
        uint32_t bdst = sb + OFF_B + buf * 16384;
        const float4* bsrc = (const float4*)(g_wB + (size_t)kt * 4096);
#pragma unroll
        for (int r = 0; r < 2; r++)
            cp_async16(bdst + (r * 512 + tid) * 16, bsrc + r * 512 + tid);
        asm volatile("cp.async.commit_group;" ::: "memory");
    };
    auto gather_load = [&](int kt, int grp) {
#pragma unroll
        for (int s = 0; s < 4; s++) {
            int ck = kt * KC + kkb + grp * 4 + s;
            int c  = ck / 9;
            int kt9 = ck - c * 9;
            ushort4 gi = gidx[kt9 * 128 + mm];
            const float* xc = xb + (c << 12);
            cor[4 * s + 0] = __ldg(xc + gi.x);
            cor[4 * s + 1] = __ldg(xc + gi.y);
            cor[4 * s + 2] = __ldg(xc + gi.z);
            cor[4 * s + 3] = __ldg(xc + gi.w);
        }
    };
    auto gather_store = [&](int kt, int grp, int buf) {
        uint32_t* ab = As + buf * 2048;
        float v[4];
#pragma unroll
        for (int s = 0; s < 4; s++) {
            int ck = kt * KC + kkb + grp * 4 + s;
            int c  = ck / 9;
            int kt9 = ck - c * 9;
            float4 wv = gwts[kt9 * 128 + mm];
            v[s] = wv.x * cor[4 * s] + wv.y * cor[4 * s + 1]
                 + wv.z * cor[4 * s + 2] + wv.w * cor[4 * s + 3];
        }
        int k2 = (kkb + grp * 4) >> 1;   // even word index base
        ab[mm * 16 + ((k2 + msw) & 15)]     = pack_h2(v[0], v[1]);
        ab[mm * 16 + ((k2 + 1 + msw) & 15)] = pack_h2(v[2], v[3]);
    };
    auto compute = [&](int buf, int k16) {
        const uint32_t* ab = As + buf * 2048;
        uint32_t a[2][4];
#pragma unroll
        for (int mt = 0; mt < 2; mt++) {
            int mr = wm * 32 + mt * 16;
            int ma = mr + g, mb2 = mr + g + 8;
            int sa = a_sw(ma), sb2 = a_sw(mb2);
            a[mt][0] = ab[ma  * 16 + ((k16 * 8 + tg + sa) & 15)];
            a[mt][1] = ab[mb2 * 16 + ((k16 * 8 + tg + sb2) & 15)];
            a[mt][2] = ab[ma  * 16 + ((k16 * 8 + 4 + tg + sa) & 15)];
            a[mt][3] = ab[mb2 * 16 + ((k16 * 8 + 4 + tg + sb2) & 15)];
        }
#pragma unroll
        for (int j = 0; j < 4; j++) {
            uint32_t b0, b1, b2, b3;
            uint32_t addr = sb + OFF_B + buf * 16384
                          + (((k16 * 16) + wn * 4 + j) * 32 + lane) * 16;
            asm volatile("ld.shared.v4.u32 {%0,%1,%2,%3}, [%4];"
                         : "=r"(b0), "=r"(b1), "=r"(b2), "=r"(b3) : "r"(addr));
            mma_f16(acc[0][2 * j],     a[0], b0, b1);
            mma_f16(acc[1][2 * j],     a[1], b0, b1);
            mma_f16(acc[0][2 * j + 1], a[0], b2, b3);
            mma_f16(acc[1][2 * j + 1], a[1], b2, b3);
        }
    };

    // prologue: stage kt=0 into buf 0
    copy_B(0, 0);
    gather_load(0, 0); gather_store(0, 0, 0);
    gather_load(0, 1); gather_store(0, 1, 0);
    asm volatile("cp.async.wait_group 0;" ::: "memory");
    __syncthreads();

    for (int kt = 0; kt < NCHUNK; kt++) {
        int buf = kt & 1;
        bool pf = (kt + 1 < NCHUNK);
        if (pf) {
            copy_B(kt + 1, buf ^ 1);
            gather_load(kt + 1, 0);
        }
        compute(buf, 0);
        if (pf) {
            gather_store(kt + 1, 0, buf ^ 1);
            gather_load(kt + 1, 1);
        }
        compute(buf, 1);
        if (pf) gather_store(kt + 1, 1, buf ^ 1);
        asm volatile("cp.async.wait_group 0;" ::: "memory");
        __syncthreads();
    }

    // epilogue: acc -> g_raw[b][n][hw]
    const int hwb = (m0 & 4095);
#pragma unroll
    for (int mt = 0; mt < 2; mt++) {
        int hw0 = hwb + wm * 32 + mt * 16 + g;
#pragma unroll
        for (int nt = 0; nt < 8; nt++) {
            int n = wn * 64 + nt * 8 + 2 * tg;
            float* p0 = g_raw + ((size_t)(b * CO + n) << 12);
            float* p1 = p0 + HW;
            p0[hw0]     = acc[mt][nt][0];
            p1[hw0]     = acc[mt][nt][1];
            p0[hw0 + 8] = acc[mt][nt][2];
            p1[hw0 + 8] = acc[mt][nt][3];
        }
    }
}

// ---------------- BN ----------------
__global__ void bn_stats(const float* __restrict__ gamma,
                         const float* __restrict__ beta) {
    int o = blockIdx.x;
    int tid = threadIdx.x;
    float s = 0.f, s2 = 0.f;
#pragma unroll
    for (int b = 0; b < BB; b++) {
        const float* p = g_raw + (size_t)((b * CO + o) << 12);
        for (int i = tid; i < HW; i += 256) {
            float v = p[i];
            s += v;
            s2 += v * v;
        }
    }
    __shared__ float sh[256], sh2[256];
    sh[tid] = s; sh2[tid] = s2;
    __syncthreads();
    for (int st = 128; st > 0; st >>= 1) {
        if (tid < st) { sh[tid] += sh[tid + st]; sh2[tid] += sh2[tid + st]; }
        __syncthreads();
    }
    if (tid == 0) {
        float mean = sh[0] * (1.f / 16384.f);
        float var  = sh2[0] * (1.f / 16384.f) - mean * mean;
        float inv  = gamma[o] * rsqrtf(var + 1e-5f);
        g_scale[o] = inv;
        g_shift[o] = beta[o] - mean * inv;
    }
}

__global__ void bn_apply(float* __restrict__ out) {
    int t = blockIdx.x * 256 + threadIdx.x;
    int o = (t >> 10) & 255;
    float4 v = ((const float4*)g_raw)[t];
    float sc = g_scale[o], sf = g_shift[o];
    float4 r;
    r.x = fmaxf(v.x * sc + sf, 0.f);
    r.y = fmaxf(v.y * sc + sf, 0.f);
    r.z = fmaxf(v.z * sc + sf, 0.f);
    r.w = fmaxf(v.w * sc + sf, 0.f);
    ((float4*)out)[t] = r;
}

// ---------------- launch ----------------
extern "C" void kernel_launch(void* const* d_in, const int* in_sizes, int n_in,
                              void* d_out, int out_size) {
    const float* x      = (const float*)d_in[0];
    const float* w_off  = (const float*)d_in[1];
    const float* b_off  = (const float*)d_in[2];
    const float* w_conv = (const float*)d_in[3];
    const float* gamma  = (const float*)d_in[4];
    const float* beta   = (const float*)d_in[5];
    float* out = (float*)d_out;

    cudaFuncSetAttribute(deform_gemm_tc,
                         cudaFuncAttributeMaxDynamicSharedMemorySize, SMEM_TOTAL);

    prep_wB<<<(NCHUNK * 4096) / 256, 256>>>(w_conv);
    offset_partial<<<dim3(BB * 16, 4), 256>>>(x, w_off);
    offset_reduce<<<(BB * 18 * HW + 255) / 256, 256>>>(b_off);
    deform_gemm_tc<<<MTOT / 128, 512, SMEM_TOTAL>>>(x);
    bn_stats<<<CO, 256>>>(gamma, beta);
    bn_apply<<<(BB * CO * HW / 4) / 256, 256>>>(out);
}